// round 1
// baseline (speedup 1.0000x reference)
#include <cuda_runtime.h>
#include <math.h>

#define B_ 2
#define N_ 2048
#define C_ 1024
#define H_ 16
#define D_ 64
#define SCALE_ 0.125f

// Scratch (allocation-free): q,k,v in [B,H,N,D]; attention output in [B,N,H,D] (= [B*N, C])
__device__ float g_q[(size_t)B_ * H_ * N_ * D_];
__device__ float g_k[(size_t)B_ * H_ * N_ * D_];
__device__ float g_v[(size_t)B_ * H_ * N_ * D_];
__device__ float g_tmp[(size_t)B_ * N_ * C_];

// ---------------------------------------------------------------------------
// Stage 1: QKV projection.  C[i,j] = sum_k x[i,k] * w_qkv[j,k]
// i in [0, 4096), j in [0, 3072), K = 1024.  Scatter into g_q/g_k/g_v [B,H,N,D].
// NT GEMM, 128x128 block tile, BK=16, 8x8 per thread, 256 threads.
// ---------------------------------------------------------------------------
#define SP 132  // smem pitch (floats): keeps float4 alignment, breaks 128-stride conflicts

__global__ __launch_bounds__(256) void qkv_gemm_kernel(const float* __restrict__ x,
                                                       const float* __restrict__ w) {
    __shared__ float As[16 * SP];
    __shared__ float Bs[16 * SP];
    const int K = C_;
    const int brow = blockIdx.y * 128;
    const int bcol = blockIdx.x * 128;
    const int tid = threadIdx.x;
    const int tm = (tid >> 4) * 8;
    const int tn = (tid & 15) * 8;

    float acc[8][8] = {};

    for (int k0 = 0; k0 < K; k0 += 16) {
#pragma unroll
        for (int i = 0; i < 2; i++) {
            int idx = tid + i * 256;        // 0..511
            int r = idx >> 2;               // 0..127
            int c4 = (idx & 3) << 2;        // 0,4,8,12
            float4 av = *(const float4*)(x + (size_t)(brow + r) * K + k0 + c4);
            As[(c4 + 0) * SP + r] = av.x;
            As[(c4 + 1) * SP + r] = av.y;
            As[(c4 + 2) * SP + r] = av.z;
            As[(c4 + 3) * SP + r] = av.w;
            float4 bv = *(const float4*)(w + (size_t)(bcol + r) * K + k0 + c4);
            Bs[(c4 + 0) * SP + r] = bv.x;
            Bs[(c4 + 1) * SP + r] = bv.y;
            Bs[(c4 + 2) * SP + r] = bv.z;
            Bs[(c4 + 3) * SP + r] = bv.w;
        }
        __syncthreads();
#pragma unroll
        for (int k = 0; k < 16; k++) {
            float a[8], bb[8];
            *(float4*)&a[0]  = *(const float4*)&As[k * SP + tm];
            *(float4*)&a[4]  = *(const float4*)&As[k * SP + tm + 4];
            *(float4*)&bb[0] = *(const float4*)&Bs[k * SP + tn];
            *(float4*)&bb[4] = *(const float4*)&Bs[k * SP + tn + 4];
#pragma unroll
            for (int i = 0; i < 8; i++)
#pragma unroll
                for (int j = 0; j < 8; j++)
                    acc[i][j] = fmaf(a[i], bb[j], acc[i][j]);
        }
        __syncthreads();
    }

    // Scatter: j -> (three, h, d); i -> (b, n)
#pragma unroll
    for (int i = 0; i < 8; i++) {
        int gi = brow + tm + i;
        int bb_ = gi >> 11;            // / 2048
        int n = gi & (N_ - 1);
#pragma unroll
        for (int j = 0; j < 8; j++) {
            int gj = bcol + tn + j;
            int three = gj >> 10;
            int h = (gj >> 6) & (H_ - 1);
            int d = gj & (D_ - 1);
            float* dst = (three == 0) ? g_q : ((three == 1) ? g_k : g_v);
            dst[(((size_t)bb_ * H_ + h) * N_ + n) * D_ + d] = acc[i][j];
        }
    }
}

// ---------------------------------------------------------------------------
// Stage 2: flash attention with MULTIPLICATIVE mask (softmax(s * mask)).
// One block = 64 query rows of one (b,h). 64-wide key tiles, online softmax.
// 256 threads; each thread owns a 4x4 patch (16 row-groups x 16 col-groups).
// Mask tile is staged through Ss and overwritten in-place with P
// (per-thread-private 4x4 region, so no extra sync needed between the two uses).
// ---------------------------------------------------------------------------
#define AP 65                       // attention smem pitch
#define ATT_SMEM (4 * 64 * AP * 4)  // Qs, Ks, Vs, Ss  = 66,560 bytes

__global__ __launch_bounds__(256) void attn_kernel(const float* __restrict__ mask) {
    extern __shared__ float sm[];
    float* Qs = sm;                 // [64][AP]
    float* Ks = sm + 64 * AP;
    float* Vs = sm + 2 * 64 * AP;
    float* Ss = sm + 3 * 64 * AP;   // mask tile, then P tile

    const int bh = blockIdx.y;            // b*H + h
    const int row0 = blockIdx.x * 64;
    const int tid = threadIdx.x;
    const int tm = (tid >> 4) * 4;        // 0..60
    const int tn = (tid & 15) * 4;        // 0..60

    const float* qp = g_q + (size_t)bh * N_ * D_;
    const float* kp = g_k + (size_t)bh * N_ * D_;
    const float* vp = g_v + (size_t)bh * N_ * D_;

    // load Q tile (float4 global reads, scalar smem stores due to odd pitch)
    for (int idx = tid; idx < 64 * 16; idx += 256) {
        int r = idx >> 4;
        int c4 = (idx & 15) << 2;
        float4 v = *(const float4*)(qp + (size_t)(row0 + r) * D_ + c4);
        Qs[r * AP + c4 + 0] = v.x;
        Qs[r * AP + c4 + 1] = v.y;
        Qs[r * AP + c4 + 2] = v.z;
        Qs[r * AP + c4 + 3] = v.w;
    }

    float o[4][4] = {};
    float mprev[4] = {-INFINITY, -INFINITY, -INFINITY, -INFINITY};
    float l[4] = {};

    for (int m0 = 0; m0 < N_; m0 += 64) {
        __syncthreads();  // prior iteration's PV reads done (also covers Q load on iter 0)
        // load K, V, mask tiles
        for (int idx = tid; idx < 64 * 16; idx += 256) {
            int r = idx >> 4;
            int c4 = (idx & 15) << 2;
            float4 kv = *(const float4*)(kp + (size_t)(m0 + r) * D_ + c4);
            Ks[r * AP + c4 + 0] = kv.x;
            Ks[r * AP + c4 + 1] = kv.y;
            Ks[r * AP + c4 + 2] = kv.z;
            Ks[r * AP + c4 + 3] = kv.w;
            float4 vv = *(const float4*)(vp + (size_t)(m0 + r) * D_ + c4);
            Vs[r * AP + c4 + 0] = vv.x;
            Vs[r * AP + c4 + 1] = vv.y;
            Vs[r * AP + c4 + 2] = vv.z;
            Vs[r * AP + c4 + 3] = vv.w;
            float4 mv = *(const float4*)(mask + (size_t)(row0 + r) * N_ + m0 + c4);
            Ss[r * AP + c4 + 0] = mv.x;
            Ss[r * AP + c4 + 1] = mv.y;
            Ss[r * AP + c4 + 2] = mv.z;
            Ss[r * AP + c4 + 3] = mv.w;
        }
        __syncthreads();

        // S = (Q K^T) * SCALE * mask
        float s[4][4] = {};
#pragma unroll
        for (int k = 0; k < 64; k++) {
            float a[4], bb[4];
#pragma unroll
            for (int i = 0; i < 4; i++) a[i] = Qs[(tm + i) * AP + k];
#pragma unroll
            for (int j = 0; j < 4; j++) bb[j] = Ks[(tn + j) * AP + k];
#pragma unroll
            for (int i = 0; i < 4; i++)
#pragma unroll
                for (int j = 0; j < 4; j++)
                    s[i][j] = fmaf(a[i], bb[j], s[i][j]);
        }
#pragma unroll
        for (int i = 0; i < 4; i++)
#pragma unroll
            for (int j = 0; j < 4; j++)
                s[i][j] *= SCALE_ * Ss[(tm + i) * AP + tn + j];

        // online softmax (row reductions over 16 aligned lanes)
#pragma unroll
        for (int i = 0; i < 4; i++) {
            float mr = fmaxf(fmaxf(s[i][0], s[i][1]), fmaxf(s[i][2], s[i][3]));
#pragma unroll
            for (int off = 8; off >= 1; off >>= 1)
                mr = fmaxf(mr, __shfl_xor_sync(0xffffffffu, mr, off));
            float mnew = fmaxf(mprev[i], mr);
            float alpha = __expf(mprev[i] - mnew);
            float rs = 0.f;
#pragma unroll
            for (int j = 0; j < 4; j++) {
                s[i][j] = __expf(s[i][j] - mnew);
                rs += s[i][j];
            }
#pragma unroll
            for (int off = 8; off >= 1; off >>= 1)
                rs += __shfl_xor_sync(0xffffffffu, rs, off);
            l[i] = l[i] * alpha + rs;
            mprev[i] = mnew;
#pragma unroll
            for (int j = 0; j < 4; j++) o[i][j] *= alpha;
        }

        // stage P (overwrite this thread's own mask patch)
#pragma unroll
        for (int i = 0; i < 4; i++)
#pragma unroll
            for (int j = 0; j < 4; j++)
                Ss[(tm + i) * AP + tn + j] = s[i][j];
        __syncthreads();

        // O += P @ V
#pragma unroll
        for (int m = 0; m < 64; m++) {
            float a[4], bb[4];
#pragma unroll
            for (int i = 0; i < 4; i++) a[i] = Ss[(tm + i) * AP + m];
#pragma unroll
            for (int j = 0; j < 4; j++) bb[j] = Vs[m * AP + tn + j];
#pragma unroll
            for (int i = 0; i < 4; i++)
#pragma unroll
                for (int j = 0; j < 4; j++)
                    o[i][j] = fmaf(a[i], bb[j], o[i][j]);
        }
    }

    // epilogue: O / l -> g_tmp [B, N, H, D]
    const int b = bh >> 4;
    const int h = bh & (H_ - 1);
#pragma unroll
    for (int i = 0; i < 4; i++) {
        float inv = 1.0f / l[i];
        int n = row0 + tm + i;
#pragma unroll
        for (int j = 0; j < 4; j++)
            g_tmp[(((size_t)b * N_ + n) * H_ + h) * D_ + tn + j] = o[i][j] * inv;
    }
}

// ---------------------------------------------------------------------------
// Stage 3: out = g_tmp @ w_proj^T + b_proj.  M=4096, N=1024, K=1024.
// ---------------------------------------------------------------------------
__global__ __launch_bounds__(256) void out_gemm_kernel(const float* __restrict__ w,
                                                       const float* __restrict__ bias,
                                                       float* __restrict__ out) {
    __shared__ float As[16 * SP];
    __shared__ float Bs[16 * SP];
    const int K = C_;
    const int brow = blockIdx.y * 128;
    const int bcol = blockIdx.x * 128;
    const int tid = threadIdx.x;
    const int tm = (tid >> 4) * 8;
    const int tn = (tid & 15) * 8;

    float acc[8][8] = {};

    for (int k0 = 0; k0 < K; k0 += 16) {
#pragma unroll
        for (int i = 0; i < 2; i++) {
            int idx = tid + i * 256;
            int r = idx >> 2;
            int c4 = (idx & 3) << 2;
            float4 av = *(const float4*)(g_tmp + (size_t)(brow + r) * K + k0 + c4);
            As[(c4 + 0) * SP + r] = av.x;
            As[(c4 + 1) * SP + r] = av.y;
            As[(c4 + 2) * SP + r] = av.z;
            As[(c4 + 3) * SP + r] = av.w;
            float4 bv = *(const float4*)(w + (size_t)(bcol + r) * K + k0 + c4);
            Bs[(c4 + 0) * SP + r] = bv.x;
            Bs[(c4 + 1) * SP + r] = bv.y;
            Bs[(c4 + 2) * SP + r] = bv.z;
            Bs[(c4 + 3) * SP + r] = bv.w;
        }
        __syncthreads();
#pragma unroll
        for (int k = 0; k < 16; k++) {
            float a[8], bb[8];
            *(float4*)&a[0]  = *(const float4*)&As[k * SP + tm];
            *(float4*)&a[4]  = *(const float4*)&As[k * SP + tm + 4];
            *(float4*)&bb[0] = *(const float4*)&Bs[k * SP + tn];
            *(float4*)&bb[4] = *(const float4*)&Bs[k * SP + tn + 4];
#pragma unroll
            for (int i = 0; i < 8; i++)
#pragma unroll
                for (int j = 0; j < 8; j++)
                    acc[i][j] = fmaf(a[i], bb[j], acc[i][j]);
        }
        __syncthreads();
    }

#pragma unroll
    for (int i = 0; i < 8; i++) {
        int gi = brow + tm + i;
#pragma unroll
        for (int j = 0; j < 8; j++) {
            int gj = bcol + tn + j;
            out[(size_t)gi * C_ + gj] = acc[i][j] + bias[gj];
        }
    }
}

// ---------------------------------------------------------------------------
extern "C" void kernel_launch(void* const* d_in, const int* in_sizes, int n_in,
                              void* d_out, int out_size) {
    const float* x      = (const float*)d_in[0];
    const float* w_qkv  = (const float*)d_in[1];
    const float* w_proj = (const float*)d_in[2];
    const float* b_proj = (const float*)d_in[3];
    const float* mask   = (const float*)d_in[4];
    float* out = (float*)d_out;

    (void)in_sizes; (void)n_in; (void)out_size;

    cudaFuncSetAttribute(attn_kernel, cudaFuncAttributeMaxDynamicSharedMemorySize, ATT_SMEM);

    // Stage 1: QKV projection (j-tiles 24 x i-tiles 32)
    qkv_gemm_kernel<<<dim3(3 * C_ / 128, (B_ * N_) / 128), 256>>>(x, w_qkv);

    // Stage 2: attention (32 q-tiles x 32 (b,h) pairs)
    attn_kernel<<<dim3(N_ / 64, B_ * H_), 256, ATT_SMEM>>>(mask);

    // Stage 3: output projection + bias
    out_gemm_kernel<<<dim3(C_ / 128, (B_ * N_) / 128), 256>>>(w_proj, b_proj, out);
}

// round 4
// speedup vs baseline: 1.3609x; 1.3609x over previous
#include <cuda_runtime.h>
#include <cuda_bf16.h>
#include <math.h>
#include <stdint.h>

#define B_ 2
#define N_ 2048
#define C_ 1024
#define H_ 16
#define D_ 64
#define SCALE_ 0.125f
#define K3 (3 * C_)   // 3072: split-K dimension (hi|lo|hi)

// ---------------------------------------------------------------------------
// Scratch (allocation-free)
// ---------------------------------------------------------------------------
__device__ float g_q[(size_t)B_ * H_ * N_ * D_];
__device__ float g_k[(size_t)B_ * H_ * N_ * D_];
__device__ float g_v[(size_t)B_ * H_ * N_ * D_];
__device__ float g_tmp[(size_t)B_ * N_ * C_];

__device__ __nv_bfloat16 g_xc [(size_t)(B_ * N_) * K3];   // x split        [4096, 3072]
__device__ __nv_bfloat16 g_wqc[(size_t)(3 * C_) * K3];    // w_qkv split    [3072, 3072]
__device__ __nv_bfloat16 g_tc [(size_t)(B_ * N_) * K3];   // attn-out split [4096, 3072]
__device__ __nv_bfloat16 g_wpc[(size_t)C_ * K3];          // w_proj split   [1024, 3072]

// ---------------------------------------------------------------------------
// PTX helpers (sm_80-era: ldmatrix / mma.sync / cp.async — valid on sm_100)
// ---------------------------------------------------------------------------
__device__ __forceinline__ uint32_t smem_u32(const void* p) {
    uint32_t a;
    asm("{ .reg .u64 t; cvta.to.shared.u64 t, %1; cvt.u32.u64 %0, t; }" : "=r"(a) : "l"(p));
    return a;
}
__device__ __forceinline__ void cp16(uint32_t dst, const void* src) {
    asm volatile("cp.async.cg.shared.global [%0], [%1], 16;" :: "r"(dst), "l"(src));
}
__device__ __forceinline__ void cp_commit() {
    asm volatile("cp.async.commit_group;");
}
__device__ __forceinline__ void cp_wait0() {
    asm volatile("cp.async.wait_group 0;");
}
__device__ __forceinline__ void ldsm4(uint32_t* r, uint32_t a) {
    asm volatile("ldmatrix.sync.aligned.m8n8.x4.shared.b16 {%0,%1,%2,%3}, [%4];"
                 : "=r"(r[0]), "=r"(r[1]), "=r"(r[2]), "=r"(r[3]) : "r"(a));
}
__device__ __forceinline__ void mma16816(float* c, const uint32_t* a, uint32_t b0, uint32_t b1) {
    asm volatile(
        "mma.sync.aligned.m16n8k16.row.col.f32.bf16.bf16.f32 "
        "{%0,%1,%2,%3}, {%4,%5,%6,%7}, {%8,%9}, {%0,%1,%2,%3};"
        : "+f"(c[0]), "+f"(c[1]), "+f"(c[2]), "+f"(c[3])
        : "r"(a[0]), "r"(a[1]), "r"(a[2]), "r"(a[3]), "r"(b0), "r"(b1));
}

// ---------------------------------------------------------------------------
// Split fp32 -> bf16 triple-wide rows.
// A-operand (activations): [hi | lo | hi]  -> ohi2 = 2K, olo = K
// B-operand (weights):     [hi | hi | lo]  -> ohi2 = K,  olo = 2K
// ---------------------------------------------------------------------------
__global__ __launch_bounds__(256) void split3_kernel(const float* __restrict__ src,
                                                     __nv_bfloat16* __restrict__ dst,
                                                     int total, int K, int ohi2, int olo) {
    int stride = gridDim.x * blockDim.x;
    for (int i4 = blockIdx.x * blockDim.x + threadIdx.x; i4 < total / 4; i4 += stride) {
        int idx = i4 * 4;
        int r = idx / K;
        int k = idx - r * K;
        float4 a = *(const float4*)(src + idx);
        __nv_bfloat16 h0 = __float2bfloat16(a.x), h1 = __float2bfloat16(a.y);
        __nv_bfloat16 h2 = __float2bfloat16(a.z), h3 = __float2bfloat16(a.w);
        __nv_bfloat16 l0 = __float2bfloat16(a.x - __bfloat162float(h0));
        __nv_bfloat16 l1 = __float2bfloat16(a.y - __bfloat162float(h1));
        __nv_bfloat16 l2 = __float2bfloat16(a.z - __bfloat162float(h2));
        __nv_bfloat16 l3 = __float2bfloat16(a.w - __bfloat162float(h3));
        size_t base = (size_t)r * (3 * K) + k;
        __nv_bfloat162 hA = {h0, h1}, hB = {h2, h3};
        __nv_bfloat162 lA = {l0, l1}, lB = {l2, l3};
        *(__nv_bfloat162*)(dst + base) = hA;
        *(__nv_bfloat162*)(dst + base + 2) = hB;
        *(__nv_bfloat162*)(dst + base + ohi2) = hA;
        *(__nv_bfloat162*)(dst + base + ohi2 + 2) = hB;
        *(__nv_bfloat162*)(dst + base + olo) = lA;
        *(__nv_bfloat162*)(dst + base + olo + 2) = lB;
    }
}

// ---------------------------------------------------------------------------
// mma.sync GEMM: D[128x128] = A''[M x 3072] @ B''[N x 3072]^T  (both K-major bf16)
// 8 warps (2 M x 4 N), warp tile 64x32, BK=32, double-buffered cp.async.
// mode 0: scatter into g_q/g_k/g_v.  mode 1: out = D + bias.
// ---------------------------------------------------------------------------
#define PITCH 40                 // bf16 elements per smem row (80B -> conflict-free ldmatrix)
#define MITERS (K3 / 32)         // 96

__global__ __launch_bounds__(256, 2) void mm_mma_kernel(const __nv_bfloat16* __restrict__ A,
                                                        const __nv_bfloat16* __restrict__ Bm,
                                                        int mode,
                                                        const float* __restrict__ bias,
                                                        float* __restrict__ outp) {
    __shared__ __nv_bfloat16 As[2][128 * PITCH];
    __shared__ __nv_bfloat16 Bs[2][128 * PITCH];

    const int tid = threadIdx.x;
    const int wid = tid >> 5;
    const int lane = tid & 31;
    const int brow = blockIdx.y * 128;
    const int bcol = blockIdx.x * 128;
    const int mbase = (wid >> 2) * 64;
    const int nbase = (wid & 3) * 32;

    const uint32_t sA[2] = {smem_u32(As[0]), smem_u32(As[1])};
    const uint32_t sB[2] = {smem_u32(Bs[0]), smem_u32(Bs[1])};

    // per-thread load coords: 512 16B-chunks per tile, 2 per thread per matrix
    const int lr0 = tid >> 1;                 // rows 0..127
    const int lq0 = (tid & 1) * 2;            // chunk col 0 or 2

    auto load_tile = [&](int kt, int buf) {
        const int k0 = kt * 32;
        const __nv_bfloat16* ap = A + (size_t)(brow + lr0) * K3 + k0;
        const __nv_bfloat16* bp = Bm + (size_t)(bcol + lr0) * K3 + k0;
        uint32_t da = sA[buf] + (lr0 * PITCH) * 2;
        uint32_t db = sB[buf] + (lr0 * PITCH) * 2;
        cp16(da + (lq0 + 0) * 16, ap + (lq0 + 0) * 8);
        cp16(da + (lq0 + 1) * 16, ap + (lq0 + 1) * 8);
        cp16(db + (lq0 + 0) * 16, bp + (lq0 + 0) * 8);
        cp16(db + (lq0 + 1) * 16, bp + (lq0 + 1) * 8);
        cp_commit();
    };

    float acc[4][4][4] = {};

    load_tile(0, 0);
    cp_wait0();
    __syncthreads();

    for (int kt = 0; kt < MITERS; kt++) {
        const int buf = kt & 1;
        if (kt + 1 < MITERS) load_tile(kt + 1, buf ^ 1);

        // compute on buf
#pragma unroll
        for (int s = 0; s < 2; s++) {
            uint32_t af[4][4];
#pragma unroll
            for (int i = 0; i < 4; i++) {
                uint32_t ad = sA[buf] +
                    ((mbase + i * 16 + (lane & 15)) * PITCH + s * 16 + (lane >> 4) * 8) * 2;
                ldsm4(af[i], ad);
            }
            uint32_t bfr[2][4];
#pragma unroll
            for (int j = 0; j < 2; j++) {
                int row = nbase + j * 16 + ((lane >> 4) & 1) * 8 + (lane & 7);
                int col = s * 16 + ((lane >> 3) & 1) * 8;
                ldsm4(bfr[j], sB[buf] + (row * PITCH + col) * 2);
            }
#pragma unroll
            for (int i = 0; i < 4; i++)
#pragma unroll
                for (int j = 0; j < 2; j++) {
                    mma16816(acc[i][2 * j],     af[i], bfr[j][0], bfr[j][1]);
                    mma16816(acc[i][2 * j + 1], af[i], bfr[j][2], bfr[j][3]);
                }
        }

        if (kt + 1 < MITERS) cp_wait0();
        __syncthreads();
    }

    // epilogue: fragment (i, jj): rows r0+i*16 (+8), cols bcol+nbase+jj*8+2*(lane&3)
    const int r0 = brow + mbase + (lane >> 2);
    const int cq = (lane & 3) * 2;
#pragma unroll
    for (int i = 0; i < 4; i++) {
#pragma unroll
        for (int jj = 0; jj < 4; jj++) {
            const float* c = acc[i][jj];
            int gc = bcol + nbase + jj * 8 + cq;
#pragma unroll
            for (int hrow = 0; hrow < 2; hrow++) {
                int gi = r0 + i * 16 + hrow * 8;
                float2 val = {c[hrow * 2 + 0], c[hrow * 2 + 1]};
                if (mode == 0) {
                    int bb = gi >> 11;
                    int nseq = gi & (N_ - 1);
                    int three = gc >> 10;
                    int h = (gc >> 6) & (H_ - 1);
                    int d = gc & (D_ - 1);
                    float* dst = (three == 0) ? g_q : ((three == 1) ? g_k : g_v);
                    *(float2*)&dst[(((size_t)bb * H_ + h) * N_ + nseq) * D_ + d] = val;
                } else {
                    val.x += bias[gc];
                    val.y += bias[gc + 1];
                    *(float2*)&outp[(size_t)gi * C_ + gc] = val;
                }
            }
        }
    }
}

// ---------------------------------------------------------------------------
// Stage 2: flash attention with MULTIPLICATIVE mask (unchanged)
// ---------------------------------------------------------------------------
#define AP 65
#define ATT_SMEM (4 * 64 * AP * 4)

__global__ __launch_bounds__(256) void attn_kernel(const float* __restrict__ mask) {
    extern __shared__ float smf[];
    float* Qs = smf;
    float* Ks = smf + 64 * AP;
    float* Vs = smf + 2 * 64 * AP;
    float* Ss = smf + 3 * 64 * AP;

    const int bh = blockIdx.y;
    const int row0 = blockIdx.x * 64;
    const int tid = threadIdx.x;
    const int tm = (tid >> 4) * 4;
    const int tn = (tid & 15) * 4;

    const float* qp = g_q + (size_t)bh * N_ * D_;
    const float* kp = g_k + (size_t)bh * N_ * D_;
    const float* vp = g_v + (size_t)bh * N_ * D_;

    for (int idx = tid; idx < 64 * 16; idx += 256) {
        int r = idx >> 4;
        int c4 = (idx & 15) << 2;
        float4 v = *(const float4*)(qp + (size_t)(row0 + r) * D_ + c4);
        Qs[r * AP + c4 + 0] = v.x;
        Qs[r * AP + c4 + 1] = v.y;
        Qs[r * AP + c4 + 2] = v.z;
        Qs[r * AP + c4 + 3] = v.w;
    }

    float o[4][4] = {};
    float mprev[4] = {-INFINITY, -INFINITY, -INFINITY, -INFINITY};
    float l[4] = {};

    for (int m0 = 0; m0 < N_; m0 += 64) {
        __syncthreads();
        for (int idx = tid; idx < 64 * 16; idx += 256) {
            int r = idx >> 4;
            int c4 = (idx & 15) << 2;
            float4 kv = *(const float4*)(kp + (size_t)(m0 + r) * D_ + c4);
            Ks[r * AP + c4 + 0] = kv.x;
            Ks[r * AP + c4 + 1] = kv.y;
            Ks[r * AP + c4 + 2] = kv.z;
            Ks[r * AP + c4 + 3] = kv.w;
            float4 vv = *(const float4*)(vp + (size_t)(m0 + r) * D_ + c4);
            Vs[r * AP + c4 + 0] = vv.x;
            Vs[r * AP + c4 + 1] = vv.y;
            Vs[r * AP + c4 + 2] = vv.z;
            Vs[r * AP + c4 + 3] = vv.w;
            float4 mv = *(const float4*)(mask + (size_t)(row0 + r) * N_ + m0 + c4);
            Ss[r * AP + c4 + 0] = mv.x;
            Ss[r * AP + c4 + 1] = mv.y;
            Ss[r * AP + c4 + 2] = mv.z;
            Ss[r * AP + c4 + 3] = mv.w;
        }
        __syncthreads();

        float s[4][4] = {};
#pragma unroll
        for (int k = 0; k < 64; k++) {
            float a[4], bb[4];
#pragma unroll
            for (int i = 0; i < 4; i++) a[i] = Qs[(tm + i) * AP + k];
#pragma unroll
            for (int j = 0; j < 4; j++) bb[j] = Ks[(tn + j) * AP + k];
#pragma unroll
            for (int i = 0; i < 4; i++)
#pragma unroll
                for (int j = 0; j < 4; j++)
                    s[i][j] = fmaf(a[i], bb[j], s[i][j]);
        }
#pragma unroll
        for (int i = 0; i < 4; i++)
#pragma unroll
            for (int j = 0; j < 4; j++)
                s[i][j] *= SCALE_ * Ss[(tm + i) * AP + tn + j];

#pragma unroll
        for (int i = 0; i < 4; i++) {
            float mr = fmaxf(fmaxf(s[i][0], s[i][1]), fmaxf(s[i][2], s[i][3]));
#pragma unroll
            for (int off = 8; off >= 1; off >>= 1)
                mr = fmaxf(mr, __shfl_xor_sync(0xffffffffu, mr, off));
            float mnew = fmaxf(mprev[i], mr);
            float alpha = __expf(mprev[i] - mnew);
            float rs = 0.f;
#pragma unroll
            for (int j = 0; j < 4; j++) {
                s[i][j] = __expf(s[i][j] - mnew);
                rs += s[i][j];
            }
#pragma unroll
            for (int off = 8; off >= 1; off >>= 1)
                rs += __shfl_xor_sync(0xffffffffu, rs, off);
            l[i] = l[i] * alpha + rs;
            mprev[i] = mnew;
#pragma unroll
            for (int j = 0; j < 4; j++) o[i][j] *= alpha;
        }

#pragma unroll
        for (int i = 0; i < 4; i++)
#pragma unroll
            for (int j = 0; j < 4; j++)
                Ss[(tm + i) * AP + tn + j] = s[i][j];
        __syncthreads();

#pragma unroll
        for (int m = 0; m < 64; m++) {
            float a[4], bb[4];
#pragma unroll
            for (int i = 0; i < 4; i++) a[i] = Ss[(tm + i) * AP + m];
#pragma unroll
            for (int j = 0; j < 4; j++) bb[j] = Vs[m * AP + tn + j];
#pragma unroll
            for (int i = 0; i < 4; i++)
#pragma unroll
                for (int j = 0; j < 4; j++)
                    o[i][j] = fmaf(a[i], bb[j], o[i][j]);
        }
    }

    const int b = bh >> 4;
    const int h = bh & (H_ - 1);
#pragma unroll
    for (int i = 0; i < 4; i++) {
        float inv = 1.0f / l[i];
        int n = row0 + tm + i;
#pragma unroll
        for (int j = 0; j < 4; j++)
            g_tmp[(((size_t)b * N_ + n) * H_ + h) * D_ + tn + j] = o[i][j] * inv;
    }
}

// ---------------------------------------------------------------------------
extern "C" void kernel_launch(void* const* d_in, const int* in_sizes, int n_in,
                              void* d_out, int out_size) {
    const float* x      = (const float*)d_in[0];
    const float* w_qkv  = (const float*)d_in[1];
    const float* w_proj = (const float*)d_in[2];
    const float* b_proj = (const float*)d_in[3];
    const float* mask   = (const float*)d_in[4];
    float* out = (float*)d_out;
    (void)in_sizes; (void)n_in; (void)out_size;

    static __nv_bfloat16 *xc = nullptr, *wqc = nullptr, *tc = nullptr, *wpc = nullptr;
    static float* tmpp = nullptr;
    static bool init_done = false;
    if (!init_done) {
        cudaFuncSetAttribute(attn_kernel, cudaFuncAttributeMaxDynamicSharedMemorySize, ATT_SMEM);
        cudaGetSymbolAddress((void**)&xc,  g_xc);
        cudaGetSymbolAddress((void**)&wqc, g_wqc);
        cudaGetSymbolAddress((void**)&tc,  g_tc);
        cudaGetSymbolAddress((void**)&wpc, g_wpc);
        cudaGetSymbolAddress((void**)&tmpp, g_tmp);
        init_done = true;
    }

    // Stage 0: fp32 -> bf16 hi/lo splits
    split3_kernel<<<1024, 256>>>(x,      xc,  B_ * N_ * C_, C_, 2 * C_, C_);  // A-type
    split3_kernel<<<1024, 256>>>(w_qkv,  wqc, 3 * C_ * C_,  C_, C_, 2 * C_);  // B-type
    split3_kernel<<<512,  256>>>(w_proj, wpc, C_ * C_,      C_, C_, 2 * C_);  // B-type

    // Stage 1: QKV projection on mma.sync tensor path
    mm_mma_kernel<<<dim3(3 * C_ / 128, (B_ * N_) / 128), 256>>>(xc, wqc, 0, nullptr, nullptr);

    // Stage 2: attention
    attn_kernel<<<dim3(N_ / 64, B_ * H_), 256, ATT_SMEM>>>(mask);

    // Stage 2.5: split attention output
    split3_kernel<<<1024, 256>>>(tmpp, tc, B_ * N_ * C_, C_, 2 * C_, C_);     // A-type

    // Stage 3: output projection + bias
    mm_mma_kernel<<<dim3(C_ / 128, (B_ * N_) / 128), 256>>>(tc, wpc, 1, b_proj, out);
}

// round 5
// speedup vs baseline: 2.3690x; 1.7407x over previous
#include <cuda_runtime.h>
#include <cuda_bf16.h>
#include <math.h>
#include <stdint.h>

#define B_ 2
#define N_ 2048
#define C_ 1024
#define H_ 16
#define D_ 64
#define SCALE_ 0.125f
#define K3 (3 * C_)   // 3072: split-K dimension (hi|lo|hi)

// ---------------------------------------------------------------------------
// Scratch (allocation-free)
// ---------------------------------------------------------------------------
__device__ __nv_bfloat16 g_qh[(size_t)B_ * H_ * N_ * D_];
__device__ __nv_bfloat16 g_ql[(size_t)B_ * H_ * N_ * D_];
__device__ __nv_bfloat16 g_kh[(size_t)B_ * H_ * N_ * D_];
__device__ __nv_bfloat16 g_kl[(size_t)B_ * H_ * N_ * D_];
__device__ __nv_bfloat16 g_vh[(size_t)B_ * H_ * N_ * D_];
__device__ __nv_bfloat16 g_vl[(size_t)B_ * H_ * N_ * D_];
__device__ __nv_bfloat16 g_maskb[(size_t)N_ * N_];

__device__ __nv_bfloat16 g_xc [(size_t)(B_ * N_) * K3];   // x split        [4096, 3072]
__device__ __nv_bfloat16 g_wqc[(size_t)(3 * C_) * K3];    // w_qkv split    [3072, 3072]
__device__ __nv_bfloat16 g_tc [(size_t)(B_ * N_) * K3];   // attn-out split [4096, 3072]
__device__ __nv_bfloat16 g_wpc[(size_t)C_ * K3];          // w_proj split   [1024, 3072]

// ---------------------------------------------------------------------------
// PTX helpers (sm_80-era: ldmatrix / mma.sync / cp.async — valid on sm_100)
// ---------------------------------------------------------------------------
__device__ __forceinline__ uint32_t smem_u32(const void* p) {
    uint32_t a;
    asm("{ .reg .u64 t; cvta.to.shared.u64 t, %1; cvt.u32.u64 %0, t; }" : "=r"(a) : "l"(p));
    return a;
}
__device__ __forceinline__ void cp16(uint32_t dst, const void* src) {
    asm volatile("cp.async.cg.shared.global [%0], [%1], 16;" :: "r"(dst), "l"(src));
}
__device__ __forceinline__ void cp_commit() {
    asm volatile("cp.async.commit_group;");
}
__device__ __forceinline__ void cp_wait0() {
    asm volatile("cp.async.wait_group 0;");
}
__device__ __forceinline__ void cp_wait1() {
    asm volatile("cp.async.wait_group 1;");
}
__device__ __forceinline__ void ldsm4(uint32_t* r, uint32_t a) {
    asm volatile("ldmatrix.sync.aligned.m8n8.x4.shared.b16 {%0,%1,%2,%3}, [%4];"
                 : "=r"(r[0]), "=r"(r[1]), "=r"(r[2]), "=r"(r[3]) : "r"(a));
}
__device__ __forceinline__ void ldsm4t(uint32_t* r, uint32_t a) {
    asm volatile("ldmatrix.sync.aligned.m8n8.x4.trans.shared.b16 {%0,%1,%2,%3}, [%4];"
                 : "=r"(r[0]), "=r"(r[1]), "=r"(r[2]), "=r"(r[3]) : "r"(a));
}
__device__ __forceinline__ void mma16816(float* c, const uint32_t* a, uint32_t b0, uint32_t b1) {
    asm volatile(
        "mma.sync.aligned.m16n8k16.row.col.f32.bf16.bf16.f32 "
        "{%0,%1,%2,%3}, {%4,%5,%6,%7}, {%8,%9}, {%0,%1,%2,%3};"
        : "+f"(c[0]), "+f"(c[1]), "+f"(c[2]), "+f"(c[3])
        : "r"(a[0]), "r"(a[1]), "r"(a[2]), "r"(a[3]), "r"(b0), "r"(b1));
}
__device__ __forceinline__ void split_pack(float a, float b, uint32_t& hp, uint32_t& lp) {
    __nv_bfloat16 ha = __float2bfloat16(a), hb = __float2bfloat16(b);
    __nv_bfloat16 la = __float2bfloat16(a - __bfloat162float(ha));
    __nv_bfloat16 lb = __float2bfloat16(b - __bfloat162float(hb));
    __nv_bfloat162 hv = {ha, hb}, lv = {la, lb};
    hp = *(uint32_t*)&hv;
    lp = *(uint32_t*)&lv;
}

// ---------------------------------------------------------------------------
// Split fp32 -> bf16 triple-wide rows.
// A-operand (activations): [hi | lo | hi]  -> ohi2 = 2K, olo = K
// B-operand (weights):     [hi | hi | lo]  -> ohi2 = K,  olo = 2K
// ---------------------------------------------------------------------------
__global__ __launch_bounds__(256) void split3_kernel(const float* __restrict__ src,
                                                     __nv_bfloat16* __restrict__ dst,
                                                     int total, int K, int ohi2, int olo) {
    int stride = gridDim.x * blockDim.x;
    for (int i4 = blockIdx.x * blockDim.x + threadIdx.x; i4 < total / 4; i4 += stride) {
        int idx = i4 * 4;
        int r = idx / K;
        int k = idx - r * K;
        float4 a = *(const float4*)(src + idx);
        __nv_bfloat16 h0 = __float2bfloat16(a.x), h1 = __float2bfloat16(a.y);
        __nv_bfloat16 h2 = __float2bfloat16(a.z), h3 = __float2bfloat16(a.w);
        __nv_bfloat16 l0 = __float2bfloat16(a.x - __bfloat162float(h0));
        __nv_bfloat16 l1 = __float2bfloat16(a.y - __bfloat162float(h1));
        __nv_bfloat16 l2 = __float2bfloat16(a.z - __bfloat162float(h2));
        __nv_bfloat16 l3 = __float2bfloat16(a.w - __bfloat162float(h3));
        size_t base = (size_t)r * (3 * K) + k;
        __nv_bfloat162 hA = {h0, h1}, hB = {h2, h3};
        __nv_bfloat162 lA = {l0, l1}, lB = {l2, l3};
        *(__nv_bfloat162*)(dst + base) = hA;
        *(__nv_bfloat162*)(dst + base + 2) = hB;
        *(__nv_bfloat162*)(dst + base + ohi2) = hA;
        *(__nv_bfloat162*)(dst + base + ohi2 + 2) = hB;
        *(__nv_bfloat162*)(dst + base + olo) = lA;
        *(__nv_bfloat162*)(dst + base + olo + 2) = lB;
    }
}

// mask fp32 -> bf16 (exact: values are 0/1)
__global__ __launch_bounds__(256) void maskconv_kernel(const float* __restrict__ m,
                                                       __nv_bfloat16* __restrict__ mb) {
    int i = blockIdx.x * blockDim.x + threadIdx.x;   // over N*N/4
    float4 v = ((const float4*)m)[i];
    __nv_bfloat162 p0 = {__float2bfloat16(v.x), __float2bfloat16(v.y)};
    __nv_bfloat162 p1 = {__float2bfloat16(v.z), __float2bfloat16(v.w)};
    ((__nv_bfloat162*)mb)[2 * i]     = p0;
    ((__nv_bfloat162*)mb)[2 * i + 1] = p1;
}

// ---------------------------------------------------------------------------
// mma.sync GEMM: D[128x128] = A''[M x 3072] @ B''[N x 3072]^T  (both K-major bf16)
// mode 0: split-scatter into g_{q,k,v}{h,l}.  mode 1: out = D + bias.
// ---------------------------------------------------------------------------
#define PITCH 40
#define MITERS (K3 / 32)         // 96

__global__ __launch_bounds__(256, 2) void mm_mma_kernel(const __nv_bfloat16* __restrict__ A,
                                                        const __nv_bfloat16* __restrict__ Bm,
                                                        int mode,
                                                        const float* __restrict__ bias,
                                                        float* __restrict__ outp) {
    __shared__ __nv_bfloat16 As[2][128 * PITCH];
    __shared__ __nv_bfloat16 Bs[2][128 * PITCH];

    const int tid = threadIdx.x;
    const int wid = tid >> 5;
    const int lane = tid & 31;
    const int brow = blockIdx.y * 128;
    const int bcol = blockIdx.x * 128;
    const int mbase = (wid >> 2) * 64;
    const int nbase = (wid & 3) * 32;

    const uint32_t sA[2] = {smem_u32(As[0]), smem_u32(As[1])};
    const uint32_t sB[2] = {smem_u32(Bs[0]), smem_u32(Bs[1])};

    const int lr0 = tid >> 1;
    const int lq0 = (tid & 1) * 2;

    auto load_tile = [&](int kt, int buf) {
        const int k0 = kt * 32;
        const __nv_bfloat16* ap = A + (size_t)(brow + lr0) * K3 + k0;
        const __nv_bfloat16* bp = Bm + (size_t)(bcol + lr0) * K3 + k0;
        uint32_t da = sA[buf] + (lr0 * PITCH) * 2;
        uint32_t db = sB[buf] + (lr0 * PITCH) * 2;
        cp16(da + (lq0 + 0) * 16, ap + (lq0 + 0) * 8);
        cp16(da + (lq0 + 1) * 16, ap + (lq0 + 1) * 8);
        cp16(db + (lq0 + 0) * 16, bp + (lq0 + 0) * 8);
        cp16(db + (lq0 + 1) * 16, bp + (lq0 + 1) * 8);
        cp_commit();
    };

    float acc[4][4][4] = {};

    load_tile(0, 0);
    cp_wait0();
    __syncthreads();

    for (int kt = 0; kt < MITERS; kt++) {
        const int buf = kt & 1;
        if (kt + 1 < MITERS) load_tile(kt + 1, buf ^ 1);

#pragma unroll
        for (int s = 0; s < 2; s++) {
            uint32_t af[4][4];
#pragma unroll
            for (int i = 0; i < 4; i++) {
                uint32_t ad = sA[buf] +
                    ((mbase + i * 16 + (lane & 15)) * PITCH + s * 16 + (lane >> 4) * 8) * 2;
                ldsm4(af[i], ad);
            }
            uint32_t bfr[2][4];
#pragma unroll
            for (int j = 0; j < 2; j++) {
                int row = nbase + j * 16 + ((lane >> 4) & 1) * 8 + (lane & 7);
                int col = s * 16 + ((lane >> 3) & 1) * 8;
                ldsm4(bfr[j], sB[buf] + (row * PITCH + col) * 2);
            }
#pragma unroll
            for (int i = 0; i < 4; i++)
#pragma unroll
                for (int j = 0; j < 2; j++) {
                    mma16816(acc[i][2 * j],     af[i], bfr[j][0], bfr[j][1]);
                    mma16816(acc[i][2 * j + 1], af[i], bfr[j][2], bfr[j][3]);
                }
        }

        if (kt + 1 < MITERS) cp_wait0();
        __syncthreads();
    }

    const int r0 = brow + mbase + (lane >> 2);
    const int cq = (lane & 3) * 2;
#pragma unroll
    for (int i = 0; i < 4; i++) {
#pragma unroll
        for (int jj = 0; jj < 4; jj++) {
            const float* c = acc[i][jj];
            int gc = bcol + nbase + jj * 8 + cq;
#pragma unroll
            for (int hrow = 0; hrow < 2; hrow++) {
                int gi = r0 + i * 16 + hrow * 8;
                float vx = c[hrow * 2 + 0], vy = c[hrow * 2 + 1];
                if (mode == 0) {
                    int bb = gi >> 11;
                    int nseq = gi & (N_ - 1);
                    int three = gc >> 10;
                    int h = (gc >> 6) & (H_ - 1);
                    int d = gc & (D_ - 1);
                    __nv_bfloat16 hx = __float2bfloat16(vx), hy = __float2bfloat16(vy);
                    __nv_bfloat16 lx = __float2bfloat16(vx - __bfloat162float(hx));
                    __nv_bfloat16 ly = __float2bfloat16(vy - __bfloat162float(hy));
                    __nv_bfloat162 hp = {hx, hy}, lp = {lx, ly};
                    __nv_bfloat16 *hd, *ld;
                    if (three == 0)      { hd = g_qh; ld = g_ql; }
                    else if (three == 1) { hd = g_kh; ld = g_kl; }
                    else                 { hd = g_vh; ld = g_vl; }
                    size_t off = (((size_t)bb * H_ + h) * N_ + nseq) * D_ + d;
                    *(__nv_bfloat162*)(hd + off) = hp;
                    *(__nv_bfloat162*)(ld + off) = lp;
                } else {
                    float2 val = {vx + bias[gc], vy + bias[gc + 1]};
                    *(float2*)&outp[(size_t)gi * C_ + gc] = val;
                }
            }
        }
    }
}

// ---------------------------------------------------------------------------
// Flash attention on mma.sync with MULTIPLICATIVE bf16 mask and 3-term splits.
// Block: 128 q-rows x one (b,h); 8 warps (m16 each); 64-key tiles, double-buffered.
// Writes normalized output directly into g_tc in [hi | lo | hi] layout.
// ---------------------------------------------------------------------------
#define QT 128
#define KT 64
#define VP 72                          // smem pitch in bf16 (144B rows, 16B aligned)
#define A_QH 0
#define A_QL (QT * VP * 2)             // 18432
#define A_BUF (2 * QT * VP * 2)        // 36864
#define A_KH 0
#define A_KL (KT * VP * 2)             // 9216
#define A_VH (2 * KT * VP * 2)
#define A_VL (3 * KT * VP * 2)
#define A_MS (4 * KT * VP * 2)         // 36864 (within buffer)
#define A_BUFSZ (4 * KT * VP * 2 + QT * VP * 2)   // 55296
#define ATT2_SMEM (A_BUF + 2 * A_BUFSZ)           // 147456

__global__ __launch_bounds__(256) void attn_mma_kernel(const __nv_bfloat16* __restrict__ maskb) {
    extern __shared__ char sm[];
    const uint32_t sb = smem_u32(sm);
    const int tid = threadIdx.x, wid = tid >> 5, lane = tid & 31;
    const int bh = blockIdx.y;
    const int row0 = blockIdx.x * QT;
    const int b = bh >> 4, h = bh & (H_ - 1);
    const size_t hoff = (size_t)bh * N_ * D_;
    const __nv_bfloat16 *qhp = g_qh + hoff, *qlp = g_ql + hoff;
    const __nv_bfloat16 *khp = g_kh + hoff, *klp = g_kl + hoff;
    const __nv_bfloat16 *vhp = g_vh + hoff, *vlp = g_vl + hoff;

    // stage Q tiles (hi & lo) into smem
    for (int idx = tid; idx < QT * 8; idx += 256) {
        int r = idx >> 3, cc = idx & 7;
        *(uint4*)(sm + A_QH + r * (VP * 2) + cc * 16) =
            *(const uint4*)(qhp + (size_t)(row0 + r) * D_ + cc * 8);
        *(uint4*)(sm + A_QL + r * (VP * 2) + cc * 16) =
            *(const uint4*)(qlp + (size_t)(row0 + r) * D_ + cc * 8);
    }
    __syncthreads();

    // Q fragments (held for whole kernel)
    const int mrow0 = wid * 16;
    uint32_t qhf[4][4], qlf[4][4];
#pragma unroll
    for (int s = 0; s < 4; s++) {
        uint32_t ad = sb + A_QH + (mrow0 + (lane & 15)) * (VP * 2) + (s * 16 + (lane >> 4) * 8) * 2;
        ldsm4(qhf[s], ad);
        ldsm4(qlf[s], ad + (A_QL - A_QH));
    }

    auto prefetch = [&](int t, uint32_t bufb) {
        const int k0 = t * KT;
#pragma unroll
        for (int i = 0; i < 2; i++) {
            int idx = tid + i * 256;
            int r = idx >> 3, cc = idx & 7;
            uint32_t ro = r * (VP * 2) + cc * 16;
            size_t go = (size_t)(k0 + r) * D_ + cc * 8;
            cp16(bufb + A_KH + ro, khp + go);
            cp16(bufb + A_KL + ro, klp + go);
            cp16(bufb + A_VH + ro, vhp + go);
            cp16(bufb + A_VL + ro, vlp + go);
        }
#pragma unroll
        for (int i = 0; i < 4; i++) {
            int idx = tid + i * 256;
            int r = idx >> 3, cc = idx & 7;
            cp16(bufb + A_MS + r * (VP * 2) + cc * 16,
                 maskb + (size_t)(row0 + r) * N_ + k0 + cc * 8);
        }
        cp_commit();
    };

    float o_acc[8][4] = {};
    float mp0 = -INFINITY, mp1 = -INFINITY, l0 = 0.f, l1 = 0.f;
    const int q2 = (lane & 3) * 2;
    const int r0l = mrow0 + (lane >> 2);    // local q row (0..119), pair row = +8

    prefetch(0, sb + A_BUF);

    for (int t = 0; t < N_ / KT; t++) {
        const uint32_t bufb = sb + A_BUF + (t & 1) * A_BUFSZ;
        if (t + 1 < N_ / KT) {
            prefetch(t + 1, sb + A_BUF + ((t + 1) & 1) * A_BUFSZ);
            cp_wait1();
        } else {
            cp_wait0();
        }
        __syncthreads();

        // ---- S = Qh·Kh + Ql·Kh + Qh·Kl ----
        float s_acc[8][4] = {};
#pragma unroll
        for (int j = 0; j < 4; j++) {
#pragma unroll
            for (int s = 0; s < 4; s++) {
                uint32_t kad = bufb + A_KH +
                    (j * 16 + ((lane >> 4) & 1) * 8 + (lane & 7)) * (VP * 2) +
                    (s * 16 + ((lane >> 3) & 1) * 8) * 2;
                uint32_t khf[4], klf[4];
                ldsm4(khf, kad);
                ldsm4(klf, kad + (A_KL - A_KH));
                mma16816(s_acc[2 * j],     qhf[s], khf[0], khf[1]);
                mma16816(s_acc[2 * j],     qlf[s], khf[0], khf[1]);
                mma16816(s_acc[2 * j],     qhf[s], klf[0], klf[1]);
                mma16816(s_acc[2 * j + 1], qhf[s], khf[2], khf[3]);
                mma16816(s_acc[2 * j + 1], qlf[s], khf[2], khf[3]);
                mma16816(s_acc[2 * j + 1], qhf[s], klf[2], klf[3]);
            }
        }

        // ---- scale * mask ----
#pragma unroll
        for (int t8 = 0; t8 < 8; t8++) {
            uint32_t mw0 = *(uint32_t*)(sm + (bufb - sb) + A_MS + r0l * (VP * 2) + (t8 * 8 + q2) * 2);
            uint32_t mw1 = *(uint32_t*)(sm + (bufb - sb) + A_MS + (r0l + 8) * (VP * 2) + (t8 * 8 + q2) * 2);
            __nv_bfloat162 m0 = *(__nv_bfloat162*)&mw0;
            __nv_bfloat162 m1 = *(__nv_bfloat162*)&mw1;
            s_acc[t8][0] *= SCALE_ * __bfloat162float(m0.x);
            s_acc[t8][1] *= SCALE_ * __bfloat162float(m0.y);
            s_acc[t8][2] *= SCALE_ * __bfloat162float(m1.x);
            s_acc[t8][3] *= SCALE_ * __bfloat162float(m1.y);
        }

        // ---- online softmax (rows r0l and r0l+8) ----
        float mx0 = -INFINITY, mx1 = -INFINITY;
#pragma unroll
        for (int t8 = 0; t8 < 8; t8++) {
            mx0 = fmaxf(mx0, fmaxf(s_acc[t8][0], s_acc[t8][1]));
            mx1 = fmaxf(mx1, fmaxf(s_acc[t8][2], s_acc[t8][3]));
        }
        mx0 = fmaxf(mx0, __shfl_xor_sync(0xffffffffu, mx0, 1));
        mx0 = fmaxf(mx0, __shfl_xor_sync(0xffffffffu, mx0, 2));
        mx1 = fmaxf(mx1, __shfl_xor_sync(0xffffffffu, mx1, 1));
        mx1 = fmaxf(mx1, __shfl_xor_sync(0xffffffffu, mx1, 2));
        float mn0 = fmaxf(mp0, mx0), mn1 = fmaxf(mp1, mx1);
        float al0 = __expf(mp0 - mn0), al1 = __expf(mp1 - mn1);
        float sum0 = 0.f, sum1 = 0.f;
        uint32_t pH[8], pH2[8], pL[8], pL2[8];
#pragma unroll
        for (int t8 = 0; t8 < 8; t8++) {
            float p0 = __expf(s_acc[t8][0] - mn0);
            float p1 = __expf(s_acc[t8][1] - mn0);
            float p2 = __expf(s_acc[t8][2] - mn1);
            float p3 = __expf(s_acc[t8][3] - mn1);
            sum0 += p0 + p1;
            sum1 += p2 + p3;
            split_pack(p0, p1, pH[t8], pL[t8]);
            split_pack(p2, p3, pH2[t8], pL2[t8]);
        }
        sum0 += __shfl_xor_sync(0xffffffffu, sum0, 1);
        sum0 += __shfl_xor_sync(0xffffffffu, sum0, 2);
        sum1 += __shfl_xor_sync(0xffffffffu, sum1, 1);
        sum1 += __shfl_xor_sync(0xffffffffu, sum1, 2);
        l0 = l0 * al0 + sum0;
        l1 = l1 * al1 + sum1;
        mp0 = mn0;
        mp1 = mn1;
#pragma unroll
        for (int t8 = 0; t8 < 8; t8++) {
            o_acc[t8][0] *= al0;
            o_acc[t8][1] *= al0;
            o_acc[t8][2] *= al1;
            o_acc[t8][3] *= al1;
        }

        // ---- O += Ph·Vh + Pl·Vh + Ph·Vl ----
#pragma unroll
        for (int nd = 0; nd < 4; nd++) {
#pragma unroll
            for (int kc = 0; kc < 4; kc++) {
                uint32_t vad = bufb + A_VH +
                    (kc * 16 + ((lane >> 3) & 1) * 8 + (lane & 7)) * (VP * 2) +
                    (nd * 16 + (lane >> 4) * 8) * 2;
                uint32_t vhf[4], vlf[4];
                ldsm4t(vhf, vad);
                ldsm4t(vlf, vad + (A_VL - A_VH));
                uint32_t ah[4]  = {pH[2 * kc], pH2[2 * kc], pH[2 * kc + 1], pH2[2 * kc + 1]};
                uint32_t alr[4] = {pL[2 * kc], pL2[2 * kc], pL[2 * kc + 1], pL2[2 * kc + 1]};
                mma16816(o_acc[2 * nd],     ah,  vhf[0], vhf[1]);
                mma16816(o_acc[2 * nd],     alr, vhf[0], vhf[1]);
                mma16816(o_acc[2 * nd],     ah,  vlf[0], vlf[1]);
                mma16816(o_acc[2 * nd + 1], ah,  vhf[2], vhf[3]);
                mma16816(o_acc[2 * nd + 1], alr, vhf[2], vhf[3]);
                mma16816(o_acc[2 * nd + 1], ah,  vlf[2], vlf[3]);
            }
        }
        __syncthreads();
    }

    // ---- epilogue: normalized output -> g_tc in [hi | lo | hi] layout ----
    float inv0 = 1.0f / l0, inv1 = 1.0f / l1;
    int n0 = row0 + r0l;
    size_t gr0 = ((size_t)b * N_ + n0) * K3;
    size_t gr1 = gr0 + (size_t)8 * K3;
#pragma unroll
    for (int t8 = 0; t8 < 8; t8++) {
        int col = h * D_ + t8 * 8 + q2;
        uint32_t hp, lp;
        split_pack(o_acc[t8][0] * inv0, o_acc[t8][1] * inv0, hp, lp);
        *(uint32_t*)(g_tc + gr0 + col)        = hp;
        *(uint32_t*)(g_tc + gr0 + col + 2048) = hp;
        *(uint32_t*)(g_tc + gr0 + col + 1024) = lp;
        split_pack(o_acc[t8][2] * inv1, o_acc[t8][3] * inv1, hp, lp);
        *(uint32_t*)(g_tc + gr1 + col)        = hp;
        *(uint32_t*)(g_tc + gr1 + col + 2048) = hp;
        *(uint32_t*)(g_tc + gr1 + col + 1024) = lp;
    }
}

// ---------------------------------------------------------------------------
extern "C" void kernel_launch(void* const* d_in, const int* in_sizes, int n_in,
                              void* d_out, int out_size) {
    const float* x      = (const float*)d_in[0];
    const float* w_qkv  = (const float*)d_in[1];
    const float* w_proj = (const float*)d_in[2];
    const float* b_proj = (const float*)d_in[3];
    const float* mask   = (const float*)d_in[4];
    float* out = (float*)d_out;
    (void)in_sizes; (void)n_in; (void)out_size;

    static __nv_bfloat16 *xc = nullptr, *wqc = nullptr, *tc = nullptr, *wpc = nullptr, *mb = nullptr;
    static bool init_done = false;
    if (!init_done) {
        cudaFuncSetAttribute(attn_mma_kernel, cudaFuncAttributeMaxDynamicSharedMemorySize, ATT2_SMEM);
        cudaGetSymbolAddress((void**)&xc,  g_xc);
        cudaGetSymbolAddress((void**)&wqc, g_wqc);
        cudaGetSymbolAddress((void**)&tc,  g_tc);
        cudaGetSymbolAddress((void**)&wpc, g_wpc);
        cudaGetSymbolAddress((void**)&mb,  g_maskb);
        init_done = true;
    }

    // Stage 0: fp32 -> bf16 splits + mask conversion
    split3_kernel<<<1024, 256>>>(x,      xc,  B_ * N_ * C_, C_, 2 * C_, C_);  // A-type
    split3_kernel<<<1024, 256>>>(w_qkv,  wqc, 3 * C_ * C_,  C_, C_, 2 * C_);  // B-type
    split3_kernel<<<512,  256>>>(w_proj, wpc, C_ * C_,      C_, C_, 2 * C_);  // B-type
    maskconv_kernel<<<(N_ * N_ / 4) / 256, 256>>>(mask, mb);

    // Stage 1: QKV projection (epilogue emits hi/lo bf16 q,k,v)
    mm_mma_kernel<<<dim3(3 * C_ / 128, (B_ * N_) / 128), 256>>>(xc, wqc, 0, nullptr, nullptr);

    // Stage 2: flash attention on tensor cores (writes g_tc directly)
    attn_mma_kernel<<<dim3(N_ / QT, B_ * H_), 256, ATT2_SMEM>>>(mb);

    // Stage 3: output projection + bias
    mm_mma_kernel<<<dim3(C_ / 128, (B_ * N_) / 128), 256>>>(tc, wpc, 1, b_proj, out);
}

// round 6
// speedup vs baseline: 2.5760x; 1.0874x over previous
#include <cuda_runtime.h>
#include <cuda_bf16.h>
#include <math.h>
#include <stdint.h>

#define B_ 2
#define N_ 2048
#define C_ 1024
#define H_ 16
#define D_ 64
#define SCALE_ 0.125f

// ---------------------------------------------------------------------------
// Scratch (allocation-free): all operands as separate hi/lo bf16 arrays
// ---------------------------------------------------------------------------
__device__ __nv_bfloat16 g_qh[(size_t)B_ * H_ * N_ * D_];
__device__ __nv_bfloat16 g_ql[(size_t)B_ * H_ * N_ * D_];
__device__ __nv_bfloat16 g_kh[(size_t)B_ * H_ * N_ * D_];
__device__ __nv_bfloat16 g_kl[(size_t)B_ * H_ * N_ * D_];
__device__ __nv_bfloat16 g_vh[(size_t)B_ * H_ * N_ * D_];
__device__ __nv_bfloat16 g_vl[(size_t)B_ * H_ * N_ * D_];
__device__ __nv_bfloat16 g_maskb[(size_t)N_ * N_];

__device__ __nv_bfloat16 g_xh [(size_t)(B_ * N_) * C_];
__device__ __nv_bfloat16 g_xl [(size_t)(B_ * N_) * C_];
__device__ __nv_bfloat16 g_wqh[(size_t)(3 * C_) * C_];
__device__ __nv_bfloat16 g_wql[(size_t)(3 * C_) * C_];
__device__ __nv_bfloat16 g_th [(size_t)(B_ * N_) * C_];
__device__ __nv_bfloat16 g_tl [(size_t)(B_ * N_) * C_];
__device__ __nv_bfloat16 g_wph[(size_t)C_ * C_];
__device__ __nv_bfloat16 g_wpl[(size_t)C_ * C_];

// ---------------------------------------------------------------------------
// PTX helpers (sm_80-era: ldmatrix / mma.sync / cp.async — valid on sm_100)
// ---------------------------------------------------------------------------
__device__ __forceinline__ uint32_t smem_u32(const void* p) {
    uint32_t a;
    asm("{ .reg .u64 t; cvta.to.shared.u64 t, %1; cvt.u32.u64 %0, t; }" : "=r"(a) : "l"(p));
    return a;
}
__device__ __forceinline__ void cp16(uint32_t dst, const void* src) {
    asm volatile("cp.async.cg.shared.global [%0], [%1], 16;" :: "r"(dst), "l"(src));
}
__device__ __forceinline__ void cp_commit() {
    asm volatile("cp.async.commit_group;");
}
__device__ __forceinline__ void cp_wait0() {
    asm volatile("cp.async.wait_group 0;");
}
__device__ __forceinline__ void cp_wait1() {
    asm volatile("cp.async.wait_group 1;");
}
__device__ __forceinline__ void ldsm4(uint32_t* r, uint32_t a) {
    asm volatile("ldmatrix.sync.aligned.m8n8.x4.shared.b16 {%0,%1,%2,%3}, [%4];"
                 : "=r"(r[0]), "=r"(r[1]), "=r"(r[2]), "=r"(r[3]) : "r"(a));
}
__device__ __forceinline__ void ldsm4t(uint32_t* r, uint32_t a) {
    asm volatile("ldmatrix.sync.aligned.m8n8.x4.trans.shared.b16 {%0,%1,%2,%3}, [%4];"
                 : "=r"(r[0]), "=r"(r[1]), "=r"(r[2]), "=r"(r[3]) : "r"(a));
}
__device__ __forceinline__ void mma16816(float* c, const uint32_t* a, uint32_t b0, uint32_t b1) {
    asm volatile(
        "mma.sync.aligned.m16n8k16.row.col.f32.bf16.bf16.f32 "
        "{%0,%1,%2,%3}, {%4,%5,%6,%7}, {%8,%9}, {%0,%1,%2,%3};"
        : "+f"(c[0]), "+f"(c[1]), "+f"(c[2]), "+f"(c[3])
        : "r"(a[0]), "r"(a[1]), "r"(a[2]), "r"(a[3]), "r"(b0), "r"(b1));
}
__device__ __forceinline__ void split_pack(float a, float b, uint32_t& hp, uint32_t& lp) {
    __nv_bfloat16 ha = __float2bfloat16(a), hb = __float2bfloat16(b);
    __nv_bfloat16 la = __float2bfloat16(a - __bfloat162float(ha));
    __nv_bfloat16 lb = __float2bfloat16(b - __bfloat162float(hb));
    __nv_bfloat162 hv = {ha, hb}, lv = {la, lb};
    hp = *(uint32_t*)&hv;
    lp = *(uint32_t*)&lv;
}

// ---------------------------------------------------------------------------
// Split fp32 -> separate hi/lo bf16 arrays (same layout as source).
// ---------------------------------------------------------------------------
__global__ __launch_bounds__(256) void split2_kernel(const float* __restrict__ src,
                                                     __nv_bfloat16* __restrict__ dh,
                                                     __nv_bfloat16* __restrict__ dl,
                                                     int total) {
    int stride = gridDim.x * blockDim.x;
    for (int i4 = blockIdx.x * blockDim.x + threadIdx.x; i4 < total / 4; i4 += stride) {
        float4 a = ((const float4*)src)[i4];
        __nv_bfloat16 h0 = __float2bfloat16(a.x), h1 = __float2bfloat16(a.y);
        __nv_bfloat16 h2 = __float2bfloat16(a.z), h3 = __float2bfloat16(a.w);
        __nv_bfloat16 l0 = __float2bfloat16(a.x - __bfloat162float(h0));
        __nv_bfloat16 l1 = __float2bfloat16(a.y - __bfloat162float(h1));
        __nv_bfloat16 l2 = __float2bfloat16(a.z - __bfloat162float(h2));
        __nv_bfloat16 l3 = __float2bfloat16(a.w - __bfloat162float(h3));
        __nv_bfloat162 hA = {h0, h1}, hB = {h2, h3};
        __nv_bfloat162 lA = {l0, l1}, lB = {l2, l3};
        ((__nv_bfloat162*)dh)[2 * i4]     = hA;
        ((__nv_bfloat162*)dh)[2 * i4 + 1] = hB;
        ((__nv_bfloat162*)dl)[2 * i4]     = lA;
        ((__nv_bfloat162*)dl)[2 * i4 + 1] = lB;
    }
}

// mask fp32 -> bf16 (exact: values are 0/1)
__global__ __launch_bounds__(256) void maskconv_kernel(const float* __restrict__ m,
                                                       __nv_bfloat16* __restrict__ mb) {
    int i = blockIdx.x * blockDim.x + threadIdx.x;   // over N*N/4
    float4 v = ((const float4*)m)[i];
    __nv_bfloat162 p0 = {__float2bfloat16(v.x), __float2bfloat16(v.y)};
    __nv_bfloat162 p1 = {__float2bfloat16(v.z), __float2bfloat16(v.w)};
    ((__nv_bfloat162*)mb)[2 * i]     = p0;
    ((__nv_bfloat162*)mb)[2 * i + 1] = p1;
}

// ---------------------------------------------------------------------------
// mma.sync GEMM with in-register 3-term split:
//   D[128x128] = Ah·Bh^T + Al·Bh^T + Ah·Bl^T,  K = 1024, BK = 32.
// 8 warps (2 M x 4 N), warp tile 64x32, double-buffered cp.async.
// mode 0: split-scatter into g_{q,k,v}{h,l}.  mode 1: out = D + bias.
// ---------------------------------------------------------------------------
#define PITCH 40
#define GK 1024
#define MITERS (GK / 32)         // 32
// smem tile offsets within one buffer (bf16 elements): Ah, Al, Bh, Bl
#define T_AH 0
#define T_AL (128 * PITCH)
#define T_BH (2 * 128 * PITCH)
#define T_BL (3 * 128 * PITCH)
#define MMBUF (4 * 128 * PITCH)              // 20480 elems = 40960 B
#define MM_SMEM (2 * MMBUF * 2)              // 81920 B

__global__ __launch_bounds__(256, 2) void mm_mma_kernel(const __nv_bfloat16* __restrict__ Ah,
                                                        const __nv_bfloat16* __restrict__ Al,
                                                        const __nv_bfloat16* __restrict__ Bh,
                                                        const __nv_bfloat16* __restrict__ Bl,
                                                        int mode,
                                                        const float* __restrict__ bias,
                                                        float* __restrict__ outp) {
    extern __shared__ __nv_bfloat16 smb[];

    const int tid = threadIdx.x;
    const int wid = tid >> 5;
    const int lane = tid & 31;
    const int brow = blockIdx.y * 128;
    const int bcol = blockIdx.x * 128;
    const int mbase = (wid >> 2) * 64;
    const int nbase = (wid & 3) * 32;

    const uint32_t sbase = smem_u32(smb);

    // per-thread load coords: each tile = 128 rows x 4 16B-chunks = 512 chunks;
    // thread covers 2 chunks per tile x 4 tiles = 8 cp16.
    const int lr0 = tid >> 1;
    const int lq0 = (tid & 1) * 2;

    auto load_tile = [&](int kt, int buf) {
        const int k0 = kt * 32;
        const size_t go = (size_t)(brow + lr0) * GK + k0;
        const size_t gob = (size_t)(bcol + lr0) * GK + k0;
        uint32_t sb = sbase + buf * (MMBUF * 2) + (lr0 * PITCH) * 2;
#pragma unroll
        for (int q = 0; q < 2; q++) {
            cp16(sb + T_AH * 2 + (lq0 + q) * 16, Ah + go  + (lq0 + q) * 8);
            cp16(sb + T_AL * 2 + (lq0 + q) * 16, Al + go  + (lq0 + q) * 8);
            cp16(sb + T_BH * 2 + (lq0 + q) * 16, Bh + gob + (lq0 + q) * 8);
            cp16(sb + T_BL * 2 + (lq0 + q) * 16, Bl + gob + (lq0 + q) * 8);
        }
        cp_commit();
    };

    float acc[4][4][4] = {};

    load_tile(0, 0);
    cp_wait0();
    __syncthreads();

    for (int kt = 0; kt < MITERS; kt++) {
        const int buf = kt & 1;
        const uint32_t sb = sbase + buf * (MMBUF * 2);
        if (kt + 1 < MITERS) load_tile(kt + 1, buf ^ 1);

#pragma unroll
        for (int s = 0; s < 2; s++) {
            // B fragments (hi & lo) for both j-halves
            uint32_t bh[2][4], bl[2][4];
#pragma unroll
            for (int j = 0; j < 2; j++) {
                int row = nbase + j * 16 + ((lane >> 4) & 1) * 8 + (lane & 7);
                int col = s * 16 + ((lane >> 3) & 1) * 8;
                uint32_t ba = sb + (row * PITCH + col) * 2;
                ldsm4(bh[j], ba + T_BH * 2);
                ldsm4(bl[j], ba + T_BL * 2);
            }
            // stream A fragments per i to bound live registers
#pragma unroll
            for (int i = 0; i < 4; i++) {
                uint32_t aa = sb +
                    ((mbase + i * 16 + (lane & 15)) * PITCH + s * 16 + (lane >> 4) * 8) * 2;
                uint32_t ah[4], al[4];
                ldsm4(ah, aa + T_AH * 2);
                ldsm4(al, aa + T_AL * 2);
#pragma unroll
                for (int j = 0; j < 2; j++) {
                    mma16816(acc[i][2 * j],     ah, bh[j][0], bh[j][1]);
                    mma16816(acc[i][2 * j],     al, bh[j][0], bh[j][1]);
                    mma16816(acc[i][2 * j],     ah, bl[j][0], bl[j][1]);
                    mma16816(acc[i][2 * j + 1], ah, bh[j][2], bh[j][3]);
                    mma16816(acc[i][2 * j + 1], al, bh[j][2], bh[j][3]);
                    mma16816(acc[i][2 * j + 1], ah, bl[j][2], bl[j][3]);
                }
            }
        }

        if (kt + 1 < MITERS) cp_wait0();
        __syncthreads();
    }

    const int r0 = brow + mbase + (lane >> 2);
    const int cq = (lane & 3) * 2;
#pragma unroll
    for (int i = 0; i < 4; i++) {
#pragma unroll
        for (int jj = 0; jj < 4; jj++) {
            const float* c = acc[i][jj];
            int gc = bcol + nbase + jj * 8 + cq;
#pragma unroll
            for (int hrow = 0; hrow < 2; hrow++) {
                int gi = r0 + i * 16 + hrow * 8;
                float vx = c[hrow * 2 + 0], vy = c[hrow * 2 + 1];
                if (mode == 0) {
                    int bb = gi >> 11;
                    int nseq = gi & (N_ - 1);
                    int three = gc >> 10;
                    int h = (gc >> 6) & (H_ - 1);
                    int d = gc & (D_ - 1);
                    uint32_t hp, lp;
                    split_pack(vx, vy, hp, lp);
                    __nv_bfloat16 *hd, *ld;
                    if (three == 0)      { hd = g_qh; ld = g_ql; }
                    else if (three == 1) { hd = g_kh; ld = g_kl; }
                    else                 { hd = g_vh; ld = g_vl; }
                    size_t off = (((size_t)bb * H_ + h) * N_ + nseq) * D_ + d;
                    *(uint32_t*)(hd + off) = hp;
                    *(uint32_t*)(ld + off) = lp;
                } else {
                    float2 val = {vx + bias[gc], vy + bias[gc + 1]};
                    *(float2*)&outp[(size_t)gi * C_ + gc] = val;
                }
            }
        }
    }
}

// ---------------------------------------------------------------------------
// Flash attention on mma.sync with MULTIPLICATIVE bf16 mask and 3-term splits.
// Block: 128 q-rows x one (b,h); 8 warps (m16 each); 64-key tiles, double-buffered.
// Writes normalized output directly into g_th/g_tl.
// ---------------------------------------------------------------------------
#define QT 128
#define KT 64
#define VP 72                          // smem pitch in bf16 (144B rows, 16B aligned)
#define A_QH 0
#define A_QL (QT * VP * 2)             // 18432
#define A_BUF (2 * QT * VP * 2)        // 36864
#define A_KH 0
#define A_KL (KT * VP * 2)             // 9216
#define A_VH (2 * KT * VP * 2)
#define A_VL (3 * KT * VP * 2)
#define A_MS (4 * KT * VP * 2)         // 36864 (within buffer)
#define A_BUFSZ (4 * KT * VP * 2 + QT * VP * 2)   // 55296
#define ATT2_SMEM (A_BUF + 2 * A_BUFSZ)           // 147456

__global__ __launch_bounds__(256) void attn_mma_kernel(const __nv_bfloat16* __restrict__ maskb) {
    extern __shared__ char sm[];
    const uint32_t sb = smem_u32(sm);
    const int tid = threadIdx.x, wid = tid >> 5, lane = tid & 31;
    const int bh = blockIdx.y;
    const int row0 = blockIdx.x * QT;
    const int b = bh >> 4, h = bh & (H_ - 1);
    const size_t hoff = (size_t)bh * N_ * D_;
    const __nv_bfloat16 *qhp = g_qh + hoff, *qlp = g_ql + hoff;
    const __nv_bfloat16 *khp = g_kh + hoff, *klp = g_kl + hoff;
    const __nv_bfloat16 *vhp = g_vh + hoff, *vlp = g_vl + hoff;

    // stage Q tiles (hi & lo) into smem
    for (int idx = tid; idx < QT * 8; idx += 256) {
        int r = idx >> 3, cc = idx & 7;
        *(uint4*)(sm + A_QH + r * (VP * 2) + cc * 16) =
            *(const uint4*)(qhp + (size_t)(row0 + r) * D_ + cc * 8);
        *(uint4*)(sm + A_QL + r * (VP * 2) + cc * 16) =
            *(const uint4*)(qlp + (size_t)(row0 + r) * D_ + cc * 8);
    }
    __syncthreads();

    // Q fragments (held for whole kernel)
    const int mrow0 = wid * 16;
    uint32_t qhf[4][4], qlf[4][4];
#pragma unroll
    for (int s = 0; s < 4; s++) {
        uint32_t ad = sb + A_QH + (mrow0 + (lane & 15)) * (VP * 2) + (s * 16 + (lane >> 4) * 8) * 2;
        ldsm4(qhf[s], ad);
        ldsm4(qlf[s], ad + (A_QL - A_QH));
    }

    auto prefetch = [&](int t, uint32_t bufb) {
        const int k0 = t * KT;
#pragma unroll
        for (int i = 0; i < 2; i++) {
            int idx = tid + i * 256;
            int r = idx >> 3, cc = idx & 7;
            uint32_t ro = r * (VP * 2) + cc * 16;
            size_t go = (size_t)(k0 + r) * D_ + cc * 8;
            cp16(bufb + A_KH + ro, khp + go);
            cp16(bufb + A_KL + ro, klp + go);
            cp16(bufb + A_VH + ro, vhp + go);
            cp16(bufb + A_VL + ro, vlp + go);
        }
#pragma unroll
        for (int i = 0; i < 4; i++) {
            int idx = tid + i * 256;
            int r = idx >> 3, cc = idx & 7;
            cp16(bufb + A_MS + r * (VP * 2) + cc * 16,
                 maskb + (size_t)(row0 + r) * N_ + k0 + cc * 8);
        }
        cp_commit();
    };

    float o_acc[8][4] = {};
    float mp0 = -INFINITY, mp1 = -INFINITY, l0 = 0.f, l1 = 0.f;
    const int q2 = (lane & 3) * 2;
    const int r0l = mrow0 + (lane >> 2);

    prefetch(0, sb + A_BUF);

    for (int t = 0; t < N_ / KT; t++) {
        const uint32_t bufb = sb + A_BUF + (t & 1) * A_BUFSZ;
        if (t + 1 < N_ / KT) {
            prefetch(t + 1, sb + A_BUF + ((t + 1) & 1) * A_BUFSZ);
            cp_wait1();
        } else {
            cp_wait0();
        }
        __syncthreads();

        // ---- S = Qh·Kh + Ql·Kh + Qh·Kl ----
        float s_acc[8][4] = {};
#pragma unroll
        for (int j = 0; j < 4; j++) {
#pragma unroll
            for (int s = 0; s < 4; s++) {
                uint32_t kad = bufb + A_KH +
                    (j * 16 + ((lane >> 4) & 1) * 8 + (lane & 7)) * (VP * 2) +
                    (s * 16 + ((lane >> 3) & 1) * 8) * 2;
                uint32_t khf[4], klf[4];
                ldsm4(khf, kad);
                ldsm4(klf, kad + (A_KL - A_KH));
                mma16816(s_acc[2 * j],     qhf[s], khf[0], khf[1]);
                mma16816(s_acc[2 * j],     qlf[s], khf[0], khf[1]);
                mma16816(s_acc[2 * j],     qhf[s], klf[0], klf[1]);
                mma16816(s_acc[2 * j + 1], qhf[s], khf[2], khf[3]);
                mma16816(s_acc[2 * j + 1], qlf[s], khf[2], khf[3]);
                mma16816(s_acc[2 * j + 1], qhf[s], klf[2], klf[3]);
            }
        }

        // ---- scale * mask ----
#pragma unroll
        for (int t8 = 0; t8 < 8; t8++) {
            uint32_t mw0 = *(uint32_t*)(sm + (bufb - sb) + A_MS + r0l * (VP * 2) + (t8 * 8 + q2) * 2);
            uint32_t mw1 = *(uint32_t*)(sm + (bufb - sb) + A_MS + (r0l + 8) * (VP * 2) + (t8 * 8 + q2) * 2);
            __nv_bfloat162 m0 = *(__nv_bfloat162*)&mw0;
            __nv_bfloat162 m1 = *(__nv_bfloat162*)&mw1;
            s_acc[t8][0] *= SCALE_ * __bfloat162float(m0.x);
            s_acc[t8][1] *= SCALE_ * __bfloat162float(m0.y);
            s_acc[t8][2] *= SCALE_ * __bfloat162float(m1.x);
            s_acc[t8][3] *= SCALE_ * __bfloat162float(m1.y);
        }

        // ---- online softmax (rows r0l and r0l+8) ----
        float mx0 = -INFINITY, mx1 = -INFINITY;
#pragma unroll
        for (int t8 = 0; t8 < 8; t8++) {
            mx0 = fmaxf(mx0, fmaxf(s_acc[t8][0], s_acc[t8][1]));
            mx1 = fmaxf(mx1, fmaxf(s_acc[t8][2], s_acc[t8][3]));
        }
        mx0 = fmaxf(mx0, __shfl_xor_sync(0xffffffffu, mx0, 1));
        mx0 = fmaxf(mx0, __shfl_xor_sync(0xffffffffu, mx0, 2));
        mx1 = fmaxf(mx1, __shfl_xor_sync(0xffffffffu, mx1, 1));
        mx1 = fmaxf(mx1, __shfl_xor_sync(0xffffffffu, mx1, 2));
        float mn0 = fmaxf(mp0, mx0), mn1 = fmaxf(mp1, mx1);
        float al0 = __expf(mp0 - mn0), al1 = __expf(mp1 - mn1);
        float sum0 = 0.f, sum1 = 0.f;
        uint32_t pH[8], pH2[8], pL[8], pL2[8];
#pragma unroll
        for (int t8 = 0; t8 < 8; t8++) {
            float p0 = __expf(s_acc[t8][0] - mn0);
            float p1 = __expf(s_acc[t8][1] - mn0);
            float p2 = __expf(s_acc[t8][2] - mn1);
            float p3 = __expf(s_acc[t8][3] - mn1);
            sum0 += p0 + p1;
            sum1 += p2 + p3;
            split_pack(p0, p1, pH[t8], pL[t8]);
            split_pack(p2, p3, pH2[t8], pL2[t8]);
        }
        sum0 += __shfl_xor_sync(0xffffffffu, sum0, 1);
        sum0 += __shfl_xor_sync(0xffffffffu, sum0, 2);
        sum1 += __shfl_xor_sync(0xffffffffu, sum1, 1);
        sum1 += __shfl_xor_sync(0xffffffffu, sum1, 2);
        l0 = l0 * al0 + sum0;
        l1 = l1 * al1 + sum1;
        mp0 = mn0;
        mp1 = mn1;
#pragma unroll
        for (int t8 = 0; t8 < 8; t8++) {
            o_acc[t8][0] *= al0;
            o_acc[t8][1] *= al0;
            o_acc[t8][2] *= al1;
            o_acc[t8][3] *= al1;
        }

        // ---- O += Ph·Vh + Pl·Vh + Ph·Vl ----
#pragma unroll
        for (int nd = 0; nd < 4; nd++) {
#pragma unroll
            for (int kc = 0; kc < 4; kc++) {
                uint32_t vad = bufb + A_VH +
                    (kc * 16 + ((lane >> 3) & 1) * 8 + (lane & 7)) * (VP * 2) +
                    (nd * 16 + (lane >> 4) * 8) * 2;
                uint32_t vhf[4], vlf[4];
                ldsm4t(vhf, vad);
                ldsm4t(vlf, vad + (A_VL - A_VH));
                uint32_t ah[4]  = {pH[2 * kc], pH2[2 * kc], pH[2 * kc + 1], pH2[2 * kc + 1]};
                uint32_t alr[4] = {pL[2 * kc], pL2[2 * kc], pL[2 * kc + 1], pL2[2 * kc + 1]};
                mma16816(o_acc[2 * nd],     ah,  vhf[0], vhf[1]);
                mma16816(o_acc[2 * nd],     alr, vhf[0], vhf[1]);
                mma16816(o_acc[2 * nd],     ah,  vlf[0], vlf[1]);
                mma16816(o_acc[2 * nd + 1], ah,  vhf[2], vhf[3]);
                mma16816(o_acc[2 * nd + 1], alr, vhf[2], vhf[3]);
                mma16816(o_acc[2 * nd + 1], ah,  vlf[2], vlf[3]);
            }
        }
        __syncthreads();
    }

    // ---- epilogue: normalized output -> g_th/g_tl [B*N, C] ----
    float inv0 = 1.0f / l0, inv1 = 1.0f / l1;
    int n0 = row0 + r0l;
    size_t gr0 = ((size_t)b * N_ + n0) * C_;
    size_t gr1 = gr0 + (size_t)8 * C_;
#pragma unroll
    for (int t8 = 0; t8 < 8; t8++) {
        int col = h * D_ + t8 * 8 + q2;
        uint32_t hp, lp;
        split_pack(o_acc[t8][0] * inv0, o_acc[t8][1] * inv0, hp, lp);
        *(uint32_t*)(g_th + gr0 + col) = hp;
        *(uint32_t*)(g_tl + gr0 + col) = lp;
        split_pack(o_acc[t8][2] * inv1, o_acc[t8][3] * inv1, hp, lp);
        *(uint32_t*)(g_th + gr1 + col) = hp;
        *(uint32_t*)(g_tl + gr1 + col) = lp;
    }
}

// ---------------------------------------------------------------------------
extern "C" void kernel_launch(void* const* d_in, const int* in_sizes, int n_in,
                              void* d_out, int out_size) {
    const float* x      = (const float*)d_in[0];
    const float* w_qkv  = (const float*)d_in[1];
    const float* w_proj = (const float*)d_in[2];
    const float* b_proj = (const float*)d_in[3];
    const float* mask   = (const float*)d_in[4];
    float* out = (float*)d_out;
    (void)in_sizes; (void)n_in; (void)out_size;

    static __nv_bfloat16 *xh = nullptr, *xl, *wqh, *wql, *th, *tl, *wph, *wpl, *mb;
    static bool init_done = false;
    if (!init_done) {
        cudaFuncSetAttribute(attn_mma_kernel, cudaFuncAttributeMaxDynamicSharedMemorySize, ATT2_SMEM);
        cudaFuncSetAttribute(mm_mma_kernel, cudaFuncAttributeMaxDynamicSharedMemorySize, MM_SMEM);
        cudaGetSymbolAddress((void**)&xh,  g_xh);
        cudaGetSymbolAddress((void**)&xl,  g_xl);
        cudaGetSymbolAddress((void**)&wqh, g_wqh);
        cudaGetSymbolAddress((void**)&wql, g_wql);
        cudaGetSymbolAddress((void**)&th,  g_th);
        cudaGetSymbolAddress((void**)&tl,  g_tl);
        cudaGetSymbolAddress((void**)&wph, g_wph);
        cudaGetSymbolAddress((void**)&wpl, g_wpl);
        cudaGetSymbolAddress((void**)&mb,  g_maskb);
        init_done = true;
    }

    // Stage 0: fp32 -> hi/lo bf16 splits + mask conversion
    split2_kernel<<<1024, 256>>>(x,      xh,  xl,  B_ * N_ * C_);
    split2_kernel<<<1024, 256>>>(w_qkv,  wqh, wql, 3 * C_ * C_);
    split2_kernel<<<512,  256>>>(w_proj, wph, wpl, C_ * C_);
    maskconv_kernel<<<(N_ * N_ / 4) / 256, 256>>>(mask, mb);

    // Stage 1: QKV projection (epilogue emits hi/lo bf16 q,k,v)
    mm_mma_kernel<<<dim3(3 * C_ / 128, (B_ * N_) / 128), 256, MM_SMEM>>>(
        xh, xl, wqh, wql, 0, nullptr, nullptr);

    // Stage 2: flash attention on tensor cores (writes g_th/g_tl directly)
    attn_mma_kernel<<<dim3(N_ / QT, B_ * H_), 256, ATT2_SMEM>>>(mb);

    // Stage 3: output projection + bias
    mm_mma_kernel<<<dim3(C_ / 128, (B_ * N_) / 128), 256, MM_SMEM>>>(
        th, tl, wph, wpl, 1, b_proj, out);
}